// round 4
// baseline (speedup 1.0000x reference)
#include <cuda_runtime.h>
#include <cuda_bf16.h>
#include <cstdint>

// Problem constants
#define KROWS 2048          // N*BS = 16*128
#define DDIM 4096
#define NTILE 16            // num_transforms, also number of 128-col tiles
#define SLAB 1572864        // BS*C*H*W floats per transform slab
#define PIC_ELEMS 25165824  // N*BS*C*H*W

// Scratch (static device globals; no runtime allocation)
__device__ __nv_bfloat16 g_sn[(size_t)KROWS * DDIM];   // normalized h, bf16 (16 MB)
__device__ float g_Epart[NTILE * KROWS];               // per-column-tile exp row sums
__device__ float g_P[KROWS * 16];                      // same-mod sims (incl diag)
__device__ float g_msepart[2048];
__device__ float g_losspart[8];

// ---------------------------------------------------------------------------
// Kernel 1: row L2 norms of h, write normalized bf16 matrix
// ---------------------------------------------------------------------------
__global__ void k_norm(const float* __restrict__ h) {
    const int row = blockIdx.x;
    const int tid = threadIdx.x;
    const float4* src = (const float4*)(h + (size_t)row * DDIM);

    float4 v[4];
    float s = 0.f;
#pragma unroll
    for (int i = 0; i < 4; i++) {
        v[i] = src[tid + i * 256];
        s += v[i].x * v[i].x + v[i].y * v[i].y + v[i].z * v[i].z + v[i].w * v[i].w;
    }

    __shared__ float wred[8];
    __shared__ float s_inv;
    const int lane = tid & 31, warp = tid >> 5;
#pragma unroll
    for (int o = 16; o > 0; o >>= 1) s += __shfl_xor_sync(0xffffffffu, s, o);
    if (lane == 0) wred[warp] = s;
    __syncthreads();
    if (tid == 0) {
        float t = 0.f;
#pragma unroll
        for (int i = 0; i < 8; i++) t += wred[i];
        s_inv = 1.f / fmaxf(sqrtf(t), 1e-8f);
    }
    __syncthreads();
    const float inv = s_inv;

    uint2* dst = (uint2*)(g_sn + (size_t)row * DDIM);
#pragma unroll
    for (int i = 0; i < 4; i++) {
        __nv_bfloat162 lo = __floats2bfloat162_rn(v[i].x * inv, v[i].y * inv);
        __nv_bfloat162 hi = __floats2bfloat162_rn(v[i].z * inv, v[i].w * inv);
        uint2 u;
        u.x = *reinterpret_cast<uint32_t*>(&lo);
        u.y = *reinterpret_cast<uint32_t*>(&hi);
        dst[tid + i * 256] = u;
    }
}

// ---------------------------------------------------------------------------
// Kernel 2: MSE between pic_set[n] and dec_pics[(n+1)%16], deterministic
// per-block partials
// ---------------------------------------------------------------------------
__global__ void k_mse(const float* __restrict__ pic, const float* __restrict__ dec) {
    const int tid = threadIdx.x;
    const int total4 = PIC_ELEMS / 4;
    const int slab4 = SLAB / 4;
    float s = 0.f;
    for (int i4 = blockIdx.x * blockDim.x + tid; i4 < total4;
         i4 += gridDim.x * blockDim.x) {
        const int n = i4 / slab4;
        const int rem4 = i4 - n * slab4;
        const int di4 = ((n + 1) & 15) * slab4 + rem4;
        const float4 a = *((const float4*)pic + i4);
        const float4 b = *((const float4*)dec + di4);
        const float dx = a.x - b.x, dy = a.y - b.y, dz = a.z - b.z, dw = a.w - b.w;
        s += dx * dx + dy * dy + dz * dz + dw * dw;
    }
    __shared__ float wred[8];
    const int lane = tid & 31, warp = tid >> 5;
#pragma unroll
    for (int o = 16; o > 0; o >>= 1) s += __shfl_xor_sync(0xffffffffu, s, o);
    if (lane == 0) wred[warp] = s;
    __syncthreads();
    if (tid == 0) {
        float t = 0.f;
#pragma unroll
        for (int i = 0; i < 8; i++) t += wred[i];
        g_msepart[blockIdx.x] = t;
    }
}

// ---------------------------------------------------------------------------
// Kernel 3: bf16 MMA GEMM  sim = sn @ sn^T  fused with exp row-sum epilogue
// and same-mod (tile-diagonal) capture.
// Block: 128x128 tile, 8 warps (2x4), warp tile 64x32, BK=32.
// ---------------------------------------------------------------------------
#define LDSS 40  // smem row stride in bf16 elems (32 + 8 pad)

__device__ __forceinline__ uint32_t smem_u32(const void* p) {
    return (uint32_t)__cvta_generic_to_shared(p);
}

__device__ __forceinline__ void ldsm4(uint32_t& r0, uint32_t& r1, uint32_t& r2,
                                      uint32_t& r3, uint32_t a) {
    asm volatile("ldmatrix.sync.aligned.m8n8.x4.shared.b16 {%0,%1,%2,%3}, [%4];\n"
                 : "=r"(r0), "=r"(r1), "=r"(r2), "=r"(r3)
                 : "r"(a));
}

__device__ __forceinline__ void mma16816(float c[4], const uint32_t a[4],
                                         const uint32_t b[2]) {
    asm volatile(
        "mma.sync.aligned.m16n8k16.row.col.f32.bf16.bf16.f32 "
        "{%0,%1,%2,%3}, {%4,%5,%6,%7}, {%8,%9}, {%0,%1,%2,%3};\n"
        : "+f"(c[0]), "+f"(c[1]), "+f"(c[2]), "+f"(c[3])
        : "r"(a[0]), "r"(a[1]), "r"(a[2]), "r"(a[3]), "r"(b[0]), "r"(b[1]));
}

__global__ void __launch_bounds__(256) k_gemm() {
    __shared__ __nv_bfloat16 As[128 * LDSS];
    __shared__ __nv_bfloat16 Bs[128 * LDSS];
    __shared__ float redbuf[128 * 4];

    const int tn = blockIdx.x, tm = blockIdx.y;
    const int tid = threadIdx.x;
    const int warp = tid >> 5, lane = tid & 31;
    const int wm = warp >> 2, wn = warp & 3;
    const int mbase = tm * 128, nbase = tn * 128;

    float acc[4][4][4];
#pragma unroll
    for (int i = 0; i < 4; i++)
#pragma unroll
        for (int j = 0; j < 4; j++)
#pragma unroll
            for (int k = 0; k < 4; k++) acc[i][j][k] = 0.f;

    const int lrow = tid >> 2;  // 0..63
    const int lc4 = tid & 3;    // which 8-elem chunk in the 32-wide row

    // ldmatrix per-thread address offsets (canonical A x4 / B-as-two-ni x4)
    const int a_row_off = ((lane >> 3) & 1) * 8 + (lane & 7);
    const int a_col_off = ((lane >> 4) & 1) * 8;
    const int b_grp = lane >> 3;
    const int b_row_off = (b_grp >> 1) * 8 + (lane & 7);
    const int b_col_off = (b_grp & 1) * 8;

    for (int kk = 0; kk < DDIM; kk += 32) {
#pragma unroll
        for (int i = 0; i < 2; i++) {
            const int r = lrow + i * 64;
            const uint4 va =
                *(const uint4*)(g_sn + (size_t)(mbase + r) * DDIM + kk + lc4 * 8);
            const uint4 vb =
                *(const uint4*)(g_sn + (size_t)(nbase + r) * DDIM + kk + lc4 * 8);
            *(uint4*)(As + r * LDSS + lc4 * 8) = va;
            *(uint4*)(Bs + r * LDSS + lc4 * 8) = vb;
        }
        __syncthreads();
#pragma unroll
        for (int ks = 0; ks < 32; ks += 16) {
            uint32_t a[4][4], b[4][2];
#pragma unroll
            for (int mi = 0; mi < 4; mi++) {
                const uint32_t ad = smem_u32(
                    As + (wm * 64 + mi * 16 + a_row_off) * LDSS + ks + a_col_off);
                ldsm4(a[mi][0], a[mi][1], a[mi][2], a[mi][3], ad);
            }
#pragma unroll
            for (int nb = 0; nb < 2; nb++) {
                const uint32_t ad = smem_u32(
                    Bs + (wn * 32 + nb * 16 + b_row_off) * LDSS + ks + b_col_off);
                uint32_t r0, r1, r2, r3;
                ldsm4(r0, r1, r2, r3, ad);
                b[nb * 2][0] = r0;
                b[nb * 2][1] = r1;
                b[nb * 2 + 1][0] = r2;
                b[nb * 2 + 1][1] = r3;
            }
#pragma unroll
            for (int mi = 0; mi < 4; mi++)
#pragma unroll
                for (int ni = 0; ni < 4; ni++) mma16816(acc[mi][ni], a[mi], b[ni]);
        }
        __syncthreads();
    }

    // Epilogue: exp(sim/temp) row sums + tile-diagonal (same-mod) capture.
    const int quad = lane >> 2, tid4 = lane & 3;
#pragma unroll
    for (int mi = 0; mi < 4; mi++) {
        float s0 = 0.f, s1 = 0.f;
        const int r0l = wm * 64 + mi * 16 + quad;
#pragma unroll
        for (int ni = 0; ni < 4; ni++) {
            const int c0l = wn * 32 + ni * 8 + tid4 * 2;
            const float v0 = acc[mi][ni][0], v1 = acc[mi][ni][1];
            const float v2 = acc[mi][ni][2], v3 = acc[mi][ni][3];
            s0 += __expf(2.f * v0) + __expf(2.f * v1);
            s1 += __expf(2.f * v2) + __expf(2.f * v3);
            if (r0l == c0l) g_P[(size_t)(mbase + r0l) * 16 + tn] = v0;
            if (r0l == c0l + 1) g_P[(size_t)(mbase + r0l) * 16 + tn] = v1;
            if (r0l + 8 == c0l) g_P[(size_t)(mbase + r0l + 8) * 16 + tn] = v2;
            if (r0l + 8 == c0l + 1) g_P[(size_t)(mbase + r0l + 8) * 16 + tn] = v3;
        }
        s0 += __shfl_xor_sync(0xffffffffu, s0, 1);
        s0 += __shfl_xor_sync(0xffffffffu, s0, 2);
        s1 += __shfl_xor_sync(0xffffffffu, s1, 1);
        s1 += __shfl_xor_sync(0xffffffffu, s1, 2);
        if (tid4 == 0) {
            redbuf[r0l * 4 + wn] = s0;
            redbuf[(r0l + 8) * 4 + wn] = s1;
        }
    }
    __syncthreads();
    if (tid < 128) {
        const float t = redbuf[tid * 4 + 0] + redbuf[tid * 4 + 1] +
                        redbuf[tid * 4 + 2] + redbuf[tid * 4 + 3];
        g_Epart[(size_t)tn * KROWS + mbase + tid] = t;
    }
}

// ---------------------------------------------------------------------------
// Kernel 4: per-row NT-Xent loss. One thread per row i.
// ---------------------------------------------------------------------------
__global__ void k_loss() {
    const int tid = threadIdx.x;
    const int i = blockIdx.x * 256 + tid;  // 8 blocks * 256 = 2048
    float contrib = 0.f;
    {
        const int nrow = i >> 7;  // i / 128
        float esum = 0.f;
#pragma unroll
        for (int t2 = 0; t2 < 16; t2++) esum += g_Epart[t2 * KROWS + i];
        float pv[16], ev[16];
        float esub = 0.f;
#pragma unroll
        for (int m = 0; m < 16; m++) {
            pv[m] = 2.f * g_P[i * 16 + m];
            ev[m] = __expf(pv[m]);
            esub += ev[m];
        }
        const float eneg = esum - esub;  // exp-sum over negatives only
#pragma unroll
        for (int m = 0; m < 16; m++)
            if (m != nrow) contrib += logf(eneg + ev[m]) - pv[m];
    }
    __shared__ float wred[8];
    const int lane = tid & 31, warp = tid >> 5;
#pragma unroll
    for (int o = 16; o > 0; o >>= 1)
        contrib += __shfl_xor_sync(0xffffffffu, contrib, o);
    if (lane == 0) wred[warp] = contrib;
    __syncthreads();
    if (tid == 0) {
        float t = 0.f;
#pragma unroll
        for (int j = 0; j < 8; j++) t += wred[j];
        g_losspart[blockIdx.x] = t;
    }
}

// ---------------------------------------------------------------------------
// Kernel 5: final combine (deterministic fixed-order reductions)
// ---------------------------------------------------------------------------
__global__ void k_final(float* __restrict__ out) {
    const int tid = threadIdx.x;
    float s = 0.f;
    for (int j = tid; j < 2048; j += 256) s += g_msepart[j];
    __shared__ float wred[8];
    const int lane = tid & 31, warp = tid >> 5;
#pragma unroll
    for (int o = 16; o > 0; o >>= 1) s += __shfl_xor_sync(0xffffffffu, s, o);
    if (lane == 0) wred[warp] = s;
    __syncthreads();
    if (tid == 0) {
        float mse = 0.f;
#pragma unroll
        for (int j = 0; j < 8; j++) mse += wred[j];
        float l = 0.f;
#pragma unroll
        for (int b = 0; b < 8; b++) l += g_losspart[b];
        out[0] = mse * (1.f / (float)PIC_ELEMS) + l * (1.f / (float)(KROWS * 15));
    }
}

// ---------------------------------------------------------------------------
extern "C" void kernel_launch(void* const* d_in, const int* in_sizes, int n_in,
                              void* d_out, int out_size) {
    (void)in_sizes; (void)n_in; (void)out_size;
    const float* pic = (const float*)d_in[0];
    const float* dec = (const float*)d_in[1];
    const float* h   = (const float*)d_in[2];

    k_norm<<<KROWS, 256>>>(h);
    k_mse<<<2048, 256>>>(pic, dec);
    k_gemm<<<dim3(16, 16), 256>>>();
    k_loss<<<8, 256>>>();
    k_final<<<1, 256>>>((float*)d_out);
}

// round 6
// speedup vs baseline: 1.7220x; 1.7220x over previous
#include <cuda_runtime.h>
#include <cuda_bf16.h>
#include <cstdint>

// Problem constants
#define KROWS 2048          // N*BS = 16*128
#define DDIM 4096
#define NTILE 16            // num_transforms, also number of 128-col tiles
#define SLAB 1572864        // BS*C*H*W floats per transform slab
#define PIC_ELEMS 25165824  // N*BS*C*H*W

// Scratch (static device globals; no runtime allocation)
__device__ __nv_bfloat16 g_sn[(size_t)KROWS * DDIM];   // normalized h, bf16 (16 MB)
__device__ float g_Epart[NTILE * KROWS];               // per-column-tile exp row sums
__device__ float g_P[KROWS * 16];                      // same-mod sims (incl diag)
__device__ float g_msepart[2048];
__device__ float g_losspart[64];

// ---------------------------------------------------------------------------
// Kernel 1: row L2 norms of h, write normalized bf16 matrix
// ---------------------------------------------------------------------------
__global__ void k_norm(const float* __restrict__ h) {
    const int row = blockIdx.x;
    const int tid = threadIdx.x;
    const float4* src = (const float4*)(h + (size_t)row * DDIM);

    float4 v[4];
    float s = 0.f;
#pragma unroll
    for (int i = 0; i < 4; i++) {
        v[i] = src[tid + i * 256];
        s += v[i].x * v[i].x + v[i].y * v[i].y + v[i].z * v[i].z + v[i].w * v[i].w;
    }

    __shared__ float wred[8];
    __shared__ float s_inv;
    const int lane = tid & 31, warp = tid >> 5;
#pragma unroll
    for (int o = 16; o > 0; o >>= 1) s += __shfl_xor_sync(0xffffffffu, s, o);
    if (lane == 0) wred[warp] = s;
    __syncthreads();
    if (tid == 0) {
        float t = 0.f;
#pragma unroll
        for (int i = 0; i < 8; i++) t += wred[i];
        s_inv = 1.f / fmaxf(sqrtf(t), 1e-8f);
    }
    __syncthreads();
    const float inv = s_inv;

    uint2* dst = (uint2*)(g_sn + (size_t)row * DDIM);
#pragma unroll
    for (int i = 0; i < 4; i++) {
        __nv_bfloat162 lo = __floats2bfloat162_rn(v[i].x * inv, v[i].y * inv);
        __nv_bfloat162 hi = __floats2bfloat162_rn(v[i].z * inv, v[i].w * inv);
        uint2 u;
        u.x = *reinterpret_cast<uint32_t*>(&lo);
        u.y = *reinterpret_cast<uint32_t*>(&hi);
        dst[tid + i * 256] = u;
    }
}

// ---------------------------------------------------------------------------
// Kernel 2: MSE between pic_set[n] and dec_pics[(n+1)%16]
// ---------------------------------------------------------------------------
__global__ void k_mse(const float* __restrict__ pic, const float* __restrict__ dec) {
    const int tid = threadIdx.x;
    const int total4 = PIC_ELEMS / 4;
    const int slab4 = SLAB / 4;
    float s = 0.f;
    for (int i4 = blockIdx.x * blockDim.x + tid; i4 < total4;
         i4 += gridDim.x * blockDim.x) {
        const int n = i4 / slab4;
        const int rem4 = i4 - n * slab4;
        const int di4 = ((n + 1) & 15) * slab4 + rem4;
        const float4 a = *((const float4*)pic + i4);
        const float4 b = *((const float4*)dec + di4);
        const float dx = a.x - b.x, dy = a.y - b.y, dz = a.z - b.z, dw = a.w - b.w;
        s += dx * dx + dy * dy + dz * dz + dw * dw;
    }
    __shared__ float wred[8];
    const int lane = tid & 31, warp = tid >> 5;
#pragma unroll
    for (int o = 16; o > 0; o >>= 1) s += __shfl_xor_sync(0xffffffffu, s, o);
    if (lane == 0) wred[warp] = s;
    __syncthreads();
    if (tid == 0) {
        float t = 0.f;
#pragma unroll
        for (int i = 0; i < 8; i++) t += wred[i];
        g_msepart[blockIdx.x] = t;
    }
}

// ---------------------------------------------------------------------------
// Kernel 3: bf16 mma.sync GEMM  sim = sn @ sn^T, upper-triangular tiles only
// (136 tiles = exactly 1 wave on 148 SMs), cp.async double-buffered BK=64,
// fused exp row-sum + col-sum epilogue and tile-diagonal capture both ways.
// Block: 128x128 tile, 8 warps (2x4), warp tile 64x32.
// ---------------------------------------------------------------------------
#define LDSS 72                      // smem row stride in bf16 (64 + 8 pad)
#define TILEB (128 * LDSS * 2)       // 18432 bytes per tile buffer
#define SMEM_TC (4 * TILEB)          // A0,A1,B0,B1 = 73728 bytes

__device__ __forceinline__ uint32_t smem_u32(const void* p) {
    return (uint32_t)__cvta_generic_to_shared(p);
}

__device__ __forceinline__ void cp_async16(uint32_t s, const void* g) {
    asm volatile("cp.async.cg.shared.global [%0], [%1], 16;\n" :: "r"(s), "l"(g));
}

__device__ __forceinline__ void ldsm4(uint32_t& r0, uint32_t& r1, uint32_t& r2,
                                      uint32_t& r3, uint32_t a) {
    asm volatile("ldmatrix.sync.aligned.m8n8.x4.shared.b16 {%0,%1,%2,%3}, [%4];\n"
                 : "=r"(r0), "=r"(r1), "=r"(r2), "=r"(r3)
                 : "r"(a));
}

__device__ __forceinline__ void mma16816(float c[4], const uint32_t a[4],
                                         const uint32_t b[2]) {
    asm volatile(
        "mma.sync.aligned.m16n8k16.row.col.f32.bf16.bf16.f32 "
        "{%0,%1,%2,%3}, {%4,%5,%6,%7}, {%8,%9}, {%0,%1,%2,%3};\n"
        : "+f"(c[0]), "+f"(c[1]), "+f"(c[2]), "+f"(c[3])
        : "r"(a[0]), "r"(a[1]), "r"(a[2]), "r"(a[3]), "r"(b[0]), "r"(b[1]));
}

__global__ void __launch_bounds__(256) k_gemm() {
    extern __shared__ char smem[];
    const int tid = threadIdx.x;
    const int warp = tid >> 5, lane = tid & 31;
    const int wm = warp >> 2, wn = warp & 3;

    // Decode upper-triangular tile index: blockIdx.x in [0,136)
    int bidx = blockIdx.x, tm = 0;
    while (bidx >= 16 - tm) { bidx -= 16 - tm; tm++; }
    const int tn = tm + bidx;
    const int mbase = tm * 128, nbase = tn * 128;

    char* const a_buf[2] = {smem, smem + TILEB};
    char* const b_buf[2] = {smem + 2 * TILEB, smem + 3 * TILEB};

    float acc[4][4][4];
#pragma unroll
    for (int i = 0; i < 4; i++)
#pragma unroll
        for (int j = 0; j < 4; j++)
#pragma unroll
            for (int k = 0; k < 4; k++) acc[i][j][k] = 0.f;

    // Loader: BK=64 chunk (128 rows x 128 bytes) for A and B via cp.async
    auto load_chunk = [&](int c, int buf) {
        const int kelem = c * 64;
        const uint32_t sa = smem_u32(a_buf[buf]);
        const uint32_t sbm = smem_u32(b_buf[buf]);
#pragma unroll
        for (int i = 0; i < 4; i++) {
            const int idx = tid + i * 256;  // 0..1023
            const int row = idx >> 3;       // 0..127
            const int c16 = idx & 7;        // 16B chunk within 128B row
            const uint32_t so = (uint32_t)(row * (LDSS * 2) + c16 * 16);
            cp_async16(sa + so,
                       g_sn + (size_t)(mbase + row) * DDIM + kelem + c16 * 8);
            cp_async16(sbm + so,
                       g_sn + (size_t)(nbase + row) * DDIM + kelem + c16 * 8);
        }
    };

    // ldmatrix per-thread address offsets (canonical A x4 / B-as-two-ni x4)
    const int a_row_off = ((lane >> 3) & 1) * 8 + (lane & 7);
    const int a_col_off = ((lane >> 4) & 1) * 8;
    const int b_grp = lane >> 3;
    const int b_row_off = (b_grp >> 1) * 8 + (lane & 7);
    const int b_col_off = (b_grp & 1) * 8;

    load_chunk(0, 0);
    asm volatile("cp.async.commit_group;\n" ::: "memory");

    for (int c = 0; c < 64; c++) {
        const int buf = c & 1;
        if (c + 1 < 64) {
            load_chunk(c + 1, buf ^ 1);
            asm volatile("cp.async.commit_group;\n" ::: "memory");
            asm volatile("cp.async.wait_group 1;\n" ::: "memory");
        } else {
            asm volatile("cp.async.wait_group 0;\n" ::: "memory");
        }
        __syncthreads();

        const __nv_bfloat16* As = (const __nv_bfloat16*)a_buf[buf];
        const __nv_bfloat16* Bs = (const __nv_bfloat16*)b_buf[buf];
#pragma unroll
        for (int ks = 0; ks < 64; ks += 16) {
            uint32_t a[4][4], b[4][2];
#pragma unroll
            for (int mi = 0; mi < 4; mi++) {
                const uint32_t ad = smem_u32(
                    As + (wm * 64 + mi * 16 + a_row_off) * LDSS + ks + a_col_off);
                ldsm4(a[mi][0], a[mi][1], a[mi][2], a[mi][3], ad);
            }
#pragma unroll
            for (int nb = 0; nb < 2; nb++) {
                const uint32_t ad = smem_u32(
                    Bs + (wn * 32 + nb * 16 + b_row_off) * LDSS + ks + b_col_off);
                uint32_t r0, r1, r2, r3;
                ldsm4(r0, r1, r2, r3, ad);
                b[nb * 2][0] = r0;
                b[nb * 2][1] = r1;
                b[nb * 2 + 1][0] = r2;
                b[nb * 2 + 1][1] = r3;
            }
#pragma unroll
            for (int mi = 0; mi < 4; mi++)
#pragma unroll
                for (int ni = 0; ni < 4; ni++) mma16816(acc[mi][ni], a[mi], b[ni]);
        }
        __syncthreads();
    }

    // Epilogue: exp(sim/temp). Row sums -> Epart[tn] rows of this tile;
    // column sums -> Epart[tm] rows of the mirrored tile; diagonal -> g_P
    // for both (row, tn) and (col, tm).
    float* redbuf = (float*)smem;            // 128 rows x 4 wn-warps
    float* colbuf = (float*)smem + 512;      // 128 cols x 2 wm-warps
    const int quad = lane >> 2, tid4 = lane & 3;

    float cs0[4], cs1[4];
#pragma unroll
    for (int ni = 0; ni < 4; ni++) { cs0[ni] = 0.f; cs1[ni] = 0.f; }

#pragma unroll
    for (int mi = 0; mi < 4; mi++) {
        float s0 = 0.f, s1 = 0.f;
        const int r0l = wm * 64 + mi * 16 + quad;
#pragma unroll
        for (int ni = 0; ni < 4; ni++) {
            const int c0l = wn * 32 + ni * 8 + tid4 * 2;
            const float v0 = acc[mi][ni][0], v1 = acc[mi][ni][1];
            const float v2 = acc[mi][ni][2], v3 = acc[mi][ni][3];
            const float e0 = __expf(2.f * v0), e1 = __expf(2.f * v1);
            const float e2 = __expf(2.f * v2), e3 = __expf(2.f * v3);
            s0 += e0 + e1;
            s1 += e2 + e3;
            cs0[ni] += e0 + e2;
            cs1[ni] += e1 + e3;
            if (r0l == c0l) {
                g_P[(size_t)(mbase + r0l) * 16 + tn] = v0;
                if (tm != tn) g_P[(size_t)(nbase + c0l) * 16 + tm] = v0;
            }
            if (r0l == c0l + 1) {
                g_P[(size_t)(mbase + r0l) * 16 + tn] = v1;
                if (tm != tn) g_P[(size_t)(nbase + c0l + 1) * 16 + tm] = v1;
            }
            if (r0l + 8 == c0l) {
                g_P[(size_t)(mbase + r0l + 8) * 16 + tn] = v2;
                if (tm != tn) g_P[(size_t)(nbase + c0l) * 16 + tm] = v2;
            }
            if (r0l + 8 == c0l + 1) {
                g_P[(size_t)(mbase + r0l + 8) * 16 + tn] = v3;
                if (tm != tn) g_P[(size_t)(nbase + c0l + 1) * 16 + tm] = v3;
            }
        }
        s0 += __shfl_xor_sync(0xffffffffu, s0, 1);
        s0 += __shfl_xor_sync(0xffffffffu, s0, 2);
        s1 += __shfl_xor_sync(0xffffffffu, s1, 1);
        s1 += __shfl_xor_sync(0xffffffffu, s1, 2);
        if (tid4 == 0) {
            redbuf[r0l * 4 + wn] = s0;
            redbuf[(r0l + 8) * 4 + wn] = s1;
        }
    }
    // Column reduce across the 8 quads (lanes differing in bits 2..4)
#pragma unroll
    for (int ni = 0; ni < 4; ni++) {
#pragma unroll
        for (int o = 4; o < 32; o <<= 1) {
            cs0[ni] += __shfl_xor_sync(0xffffffffu, cs0[ni], o);
            cs1[ni] += __shfl_xor_sync(0xffffffffu, cs1[ni], o);
        }
        if (lane < 4) {  // quad==0, tid4==lane
            const int col = wn * 32 + ni * 8 + lane * 2;
            colbuf[col * 2 + wm] = cs0[ni];
            colbuf[(col + 1) * 2 + wm] = cs1[ni];
        }
    }
    __syncthreads();
    if (tid < 128) {
        const float t = redbuf[tid * 4 + 0] + redbuf[tid * 4 + 1] +
                        redbuf[tid * 4 + 2] + redbuf[tid * 4 + 3];
        g_Epart[(size_t)tn * KROWS + mbase + tid] = t;
        if (tm != tn) {
            const float cst = colbuf[tid * 2 + 0] + colbuf[tid * 2 + 1];
            g_Epart[(size_t)tm * KROWS + nbase + tid] = cst;
        }
    }
}

// ---------------------------------------------------------------------------
// Kernel 4: per-row NT-Xent loss. One thread per row; 64 blocks x 32 threads.
// ---------------------------------------------------------------------------
__global__ void k_loss() {
    const int tid = threadIdx.x;
    const int i = blockIdx.x * 32 + tid;  // 64*32 = 2048
    float contrib = 0.f;
    {
        const int nrow = i >> 7;  // i / 128
        float esum = 0.f;
#pragma unroll
        for (int t2 = 0; t2 < 16; t2++) esum += g_Epart[t2 * KROWS + i];
        float pv[16], ev[16];
        float esub = 0.f;
#pragma unroll
        for (int m = 0; m < 16; m++) {
            pv[m] = 2.f * g_P[i * 16 + m];
            ev[m] = __expf(pv[m]);
            esub += ev[m];
        }
        const float eneg = esum - esub;  // exp-sum over negatives only
#pragma unroll
        for (int m = 0; m < 16; m++)
            if (m != nrow) contrib += logf(eneg + ev[m]) - pv[m];
    }
#pragma unroll
    for (int o = 16; o > 0; o >>= 1)
        contrib += __shfl_xor_sync(0xffffffffu, contrib, o);
    if (tid == 0) g_losspart[blockIdx.x] = contrib;
}

// ---------------------------------------------------------------------------
// Kernel 5: final combine (deterministic fixed-order reductions)
// ---------------------------------------------------------------------------
__global__ void k_final(float* __restrict__ out) {
    const int tid = threadIdx.x;
    float s = 0.f;
    for (int j = tid; j < 2048; j += 256) s += g_msepart[j];
    __shared__ float wred[8];
    const int lane = tid & 31, warp = tid >> 5;
#pragma unroll
    for (int o = 16; o > 0; o >>= 1) s += __shfl_xor_sync(0xffffffffu, s, o);
    if (lane == 0) wred[warp] = s;
    __syncthreads();
    if (tid == 0) {
        float mse = 0.f;
#pragma unroll
        for (int j = 0; j < 8; j++) mse += wred[j];
        float l = 0.f;
#pragma unroll
        for (int b = 0; b < 64; b++) l += g_losspart[b];
        out[0] = mse * (1.f / (float)PIC_ELEMS) + l * (1.f / (float)(KROWS * 15));
    }
}

// ---------------------------------------------------------------------------
extern "C" void kernel_launch(void* const* d_in, const int* in_sizes, int n_in,
                              void* d_out, int out_size) {
    (void)in_sizes; (void)n_in; (void)out_size;
    const float* pic = (const float*)d_in[0];
    const float* dec = (const float*)d_in[1];
    const float* h   = (const float*)d_in[2];

    // Raise dynamic smem limit for the GEMM (73728 B > default 48 KB).
    // Idempotent host-side call; not a stream op, safe under graph capture.
    cudaFuncSetAttribute(k_gemm, cudaFuncAttributeMaxDynamicSharedMemorySize,
                         SMEM_TC);

    k_norm<<<KROWS, 256>>>(h);
    k_mse<<<2048, 256>>>(pic, dec);
    k_gemm<<<136, 256, SMEM_TC>>>();
    k_loss<<<64, 32>>>();
    k_final<<<1, 256>>>((float*)d_out);
}

// round 7
// speedup vs baseline: 1.7326x; 1.0061x over previous
#include <cuda_runtime.h>
#include <cuda_bf16.h>
#include <cstdint>

// Problem constants
#define KROWS 2048          // N*BS = 16*128
#define DDIM 4096
#define NTILE 16            // num_transforms, also number of 128-col tiles
#define SLAB 1572864        // BS*C*H*W floats per transform slab
#define PIC_ELEMS 25165824  // N*BS*C*H*W

// Scratch (static device globals; no runtime allocation)
__device__ __nv_bfloat16 g_sn[(size_t)KROWS * DDIM];   // normalized h, bf16 (16 MB)
__device__ float g_Epart[NTILE * KROWS];               // per-column-tile exp row sums
__device__ float g_P[KROWS * 16];                      // same-mod sims (incl diag)
__device__ float g_msepart[2048];
__device__ float g_losspart[64];

// ---------------------------------------------------------------------------
// Kernel 1: row L2 norms of h, write normalized bf16 matrix
// ---------------------------------------------------------------------------
__global__ void k_norm(const float* __restrict__ h) {
    const int row = blockIdx.x;
    const int tid = threadIdx.x;
    const float4* src = (const float4*)(h + (size_t)row * DDIM);

    float4 v[4];
    float s = 0.f;
#pragma unroll
    for (int i = 0; i < 4; i++) {
        v[i] = src[tid + i * 256];
        s += v[i].x * v[i].x + v[i].y * v[i].y + v[i].z * v[i].z + v[i].w * v[i].w;
    }

    __shared__ float wred[8];
    __shared__ float s_inv;
    const int lane = tid & 31, warp = tid >> 5;
#pragma unroll
    for (int o = 16; o > 0; o >>= 1) s += __shfl_xor_sync(0xffffffffu, s, o);
    if (lane == 0) wred[warp] = s;
    __syncthreads();
    if (tid == 0) {
        float t = 0.f;
#pragma unroll
        for (int i = 0; i < 8; i++) t += wred[i];
        s_inv = 1.f / fmaxf(sqrtf(t), 1e-8f);
    }
    __syncthreads();
    const float inv = s_inv;

    uint2* dst = (uint2*)(g_sn + (size_t)row * DDIM);
#pragma unroll
    for (int i = 0; i < 4; i++) {
        __nv_bfloat162 lo = __floats2bfloat162_rn(v[i].x * inv, v[i].y * inv);
        __nv_bfloat162 hi = __floats2bfloat162_rn(v[i].z * inv, v[i].w * inv);
        uint2 u;
        u.x = *reinterpret_cast<uint32_t*>(&lo);
        u.y = *reinterpret_cast<uint32_t*>(&hi);
        dst[tid + i * 256] = u;
    }
}

// ---------------------------------------------------------------------------
// Kernel 2: MSE between pic_set[n] and dec_pics[(n+1)%16]
// ---------------------------------------------------------------------------
__global__ void k_mse(const float* __restrict__ pic, const float* __restrict__ dec) {
    const int tid = threadIdx.x;
    const int total4 = PIC_ELEMS / 4;
    const int slab4 = SLAB / 4;
    float s = 0.f;
    for (int i4 = blockIdx.x * blockDim.x + tid; i4 < total4;
         i4 += gridDim.x * blockDim.x) {
        const int n = i4 / slab4;
        const int rem4 = i4 - n * slab4;
        const int di4 = ((n + 1) & 15) * slab4 + rem4;
        const float4 a = *((const float4*)pic + i4);
        const float4 b = *((const float4*)dec + di4);
        const float dx = a.x - b.x, dy = a.y - b.y, dz = a.z - b.z, dw = a.w - b.w;
        s += dx * dx + dy * dy + dz * dz + dw * dw;
    }
    __shared__ float wred[8];
    const int lane = tid & 31, warp = tid >> 5;
#pragma unroll
    for (int o = 16; o > 0; o >>= 1) s += __shfl_xor_sync(0xffffffffu, s, o);
    if (lane == 0) wred[warp] = s;
    __syncthreads();
    if (tid == 0) {
        float t = 0.f;
#pragma unroll
        for (int i = 0; i < 8; i++) t += wred[i];
        g_msepart[blockIdx.x] = t;
    }
}

// ---------------------------------------------------------------------------
// Kernel 3: bf16 mma.sync GEMM  sim = sn @ sn^T, upper-triangular tiles only
// (136 tiles = exactly 1 wave on 148 SMs), cp.async 4-stage pipeline BK=64,
// fused exp row-sum + col-sum epilogue and tile-diagonal capture both ways.
// Block: 128x128 tile, 8 warps (2x4), warp tile 64x32.
// ---------------------------------------------------------------------------
#define LDSS 72                      // smem row stride in bf16 (64 + 8 pad)
#define TILEB (128 * LDSS * 2)       // 18432 bytes per tile buffer
#define STAGEB (2 * TILEB)           // A+B per stage = 36864
#define STAGES 4
#define SMEM_TC (STAGES * STAGEB)    // 147456 bytes

__device__ __forceinline__ uint32_t smem_u32(const void* p) {
    return (uint32_t)__cvta_generic_to_shared(p);
}

__device__ __forceinline__ void cp_async16(uint32_t s, const void* g) {
    asm volatile("cp.async.cg.shared.global [%0], [%1], 16;\n" :: "r"(s), "l"(g));
}

__device__ __forceinline__ void ldsm4(uint32_t& r0, uint32_t& r1, uint32_t& r2,
                                      uint32_t& r3, uint32_t a) {
    asm volatile("ldmatrix.sync.aligned.m8n8.x4.shared.b16 {%0,%1,%2,%3}, [%4];\n"
                 : "=r"(r0), "=r"(r1), "=r"(r2), "=r"(r3)
                 : "r"(a));
}

__device__ __forceinline__ void mma16816(float c[4], const uint32_t a[4],
                                         const uint32_t b[2]) {
    asm volatile(
        "mma.sync.aligned.m16n8k16.row.col.f32.bf16.bf16.f32 "
        "{%0,%1,%2,%3}, {%4,%5,%6,%7}, {%8,%9}, {%0,%1,%2,%3};\n"
        : "+f"(c[0]), "+f"(c[1]), "+f"(c[2]), "+f"(c[3])
        : "r"(a[0]), "r"(a[1]), "r"(a[2]), "r"(a[3]), "r"(b[0]), "r"(b[1]));
}

__global__ void __launch_bounds__(256) k_gemm() {
    extern __shared__ char smem[];
    const int tid = threadIdx.x;
    const int warp = tid >> 5, lane = tid & 31;
    const int wm = warp >> 2, wn = warp & 3;

    // Decode upper-triangular tile index: blockIdx.x in [0,136)
    int bidx = blockIdx.x, tm = 0;
    while (bidx >= 16 - tm) { bidx -= 16 - tm; tm++; }
    const int tn = tm + bidx;
    const int mbase = tm * 128, nbase = tn * 128;

    float acc[4][4][4];
#pragma unroll
    for (int i = 0; i < 4; i++)
#pragma unroll
        for (int j = 0; j < 4; j++)
#pragma unroll
            for (int k = 0; k < 4; k++) acc[i][j][k] = 0.f;

    // Loader: BK=64 chunk (128 rows x 128 bytes) for A and B via cp.async
    auto load_chunk = [&](int c, int stg) {
        const int kelem = c * 64;
        const uint32_t sa = smem_u32(smem + stg * STAGEB);
        const uint32_t sbm = sa + TILEB;
#pragma unroll
        for (int i = 0; i < 4; i++) {
            const int idx = tid + i * 256;  // 0..1023
            const int row = idx >> 3;       // 0..127
            const int c16 = idx & 7;        // 16B chunk within 128B row
            const uint32_t so = (uint32_t)(row * (LDSS * 2) + c16 * 16);
            cp_async16(sa + so,
                       g_sn + (size_t)(mbase + row) * DDIM + kelem + c16 * 8);
            cp_async16(sbm + so,
                       g_sn + (size_t)(nbase + row) * DDIM + kelem + c16 * 8);
        }
        asm volatile("cp.async.commit_group;\n" ::: "memory");
    };

    // ldmatrix per-thread address offsets (canonical A x4 / B-as-two-ni x4)
    const int a_row_off = ((lane >> 3) & 1) * 8 + (lane & 7);
    const int a_col_off = ((lane >> 4) & 1) * 8;
    const int b_grp = lane >> 3;
    const int b_row_off = (b_grp >> 1) * 8 + (lane & 7);
    const int b_col_off = (b_grp & 1) * 8;

#pragma unroll
    for (int s = 0; s < STAGES - 1; s++) load_chunk(s, s);

    for (int c = 0; c < 64; c++) {
        const int stg = c & (STAGES - 1);
        if (c + STAGES - 1 < 64) load_chunk(c + STAGES - 1, (c + STAGES - 1) & (STAGES - 1));
        // Ensure chunk c's group has completed.
        if (c <= 61) {
            asm volatile("cp.async.wait_group 2;\n" ::: "memory");
        } else if (c == 62) {
            asm volatile("cp.async.wait_group 1;\n" ::: "memory");
        } else {
            asm volatile("cp.async.wait_group 0;\n" ::: "memory");
        }
        __syncthreads();

        const __nv_bfloat16* As = (const __nv_bfloat16*)(smem + stg * STAGEB);
        const __nv_bfloat16* Bs = (const __nv_bfloat16*)(smem + stg * STAGEB + TILEB);
#pragma unroll
        for (int ks = 0; ks < 64; ks += 16) {
            uint32_t a[4][4], b[4][2];
#pragma unroll
            for (int mi = 0; mi < 4; mi++) {
                const uint32_t ad = smem_u32(
                    As + (wm * 64 + mi * 16 + a_row_off) * LDSS + ks + a_col_off);
                ldsm4(a[mi][0], a[mi][1], a[mi][2], a[mi][3], ad);
            }
#pragma unroll
            for (int nb = 0; nb < 2; nb++) {
                const uint32_t ad = smem_u32(
                    Bs + (wn * 32 + nb * 16 + b_row_off) * LDSS + ks + b_col_off);
                uint32_t r0, r1, r2, r3;
                ldsm4(r0, r1, r2, r3, ad);
                b[nb * 2][0] = r0;
                b[nb * 2][1] = r1;
                b[nb * 2 + 1][0] = r2;
                b[nb * 2 + 1][1] = r3;
            }
#pragma unroll
            for (int mi = 0; mi < 4; mi++)
#pragma unroll
                for (int ni = 0; ni < 4; ni++) mma16816(acc[mi][ni], a[mi], b[ni]);
        }
        __syncthreads();  // all warps done reading stage stg before it is reloaded
    }

    // Epilogue: exp(sim/temp). Row sums -> Epart[tn] rows of this tile;
    // column sums -> Epart[tm] rows of the mirrored tile; diagonal -> g_P
    // for both (row, tn) and (col, tm).
    float* redbuf = (float*)smem;            // 128 rows x 4 wn-warps
    float* colbuf = (float*)smem + 512;      // 128 cols x 2 wm-warps
    const int quad = lane >> 2, tid4 = lane & 3;

    float cs0[4], cs1[4];
#pragma unroll
    for (int ni = 0; ni < 4; ni++) { cs0[ni] = 0.f; cs1[ni] = 0.f; }

#pragma unroll
    for (int mi = 0; mi < 4; mi++) {
        float s0 = 0.f, s1 = 0.f;
        const int r0l = wm * 64 + mi * 16 + quad;
#pragma unroll
        for (int ni = 0; ni < 4; ni++) {
            const int c0l = wn * 32 + ni * 8 + tid4 * 2;
            const float v0 = acc[mi][ni][0], v1 = acc[mi][ni][1];
            const float v2 = acc[mi][ni][2], v3 = acc[mi][ni][3];
            const float e0 = __expf(2.f * v0), e1 = __expf(2.f * v1);
            const float e2 = __expf(2.f * v2), e3 = __expf(2.f * v3);
            s0 += e0 + e1;
            s1 += e2 + e3;
            cs0[ni] += e0 + e2;
            cs1[ni] += e1 + e3;
            if (r0l == c0l) {
                g_P[(size_t)(mbase + r0l) * 16 + tn] = v0;
                if (tm != tn) g_P[(size_t)(nbase + c0l) * 16 + tm] = v0;
            }
            if (r0l == c0l + 1) {
                g_P[(size_t)(mbase + r0l) * 16 + tn] = v1;
                if (tm != tn) g_P[(size_t)(nbase + c0l + 1) * 16 + tm] = v1;
            }
            if (r0l + 8 == c0l) {
                g_P[(size_t)(mbase + r0l + 8) * 16 + tn] = v2;
                if (tm != tn) g_P[(size_t)(nbase + c0l) * 16 + tm] = v2;
            }
            if (r0l + 8 == c0l + 1) {
                g_P[(size_t)(mbase + r0l + 8) * 16 + tn] = v3;
                if (tm != tn) g_P[(size_t)(nbase + c0l + 1) * 16 + tm] = v3;
            }
        }
        s0 += __shfl_xor_sync(0xffffffffu, s0, 1);
        s0 += __shfl_xor_sync(0xffffffffu, s0, 2);
        s1 += __shfl_xor_sync(0xffffffffu, s1, 1);
        s1 += __shfl_xor_sync(0xffffffffu, s1, 2);
        if (tid4 == 0) {
            redbuf[r0l * 4 + wn] = s0;
            redbuf[(r0l + 8) * 4 + wn] = s1;
        }
    }
    // Column reduce across the 8 quads (lanes differing in bits 2..4)
#pragma unroll
    for (int ni = 0; ni < 4; ni++) {
#pragma unroll
        for (int o = 4; o < 32; o <<= 1) {
            cs0[ni] += __shfl_xor_sync(0xffffffffu, cs0[ni], o);
            cs1[ni] += __shfl_xor_sync(0xffffffffu, cs1[ni], o);
        }
        if (lane < 4) {  // quad==0, tid4==lane
            const int col = wn * 32 + ni * 8 + lane * 2;
            colbuf[col * 2 + wm] = cs0[ni];
            colbuf[(col + 1) * 2 + wm] = cs1[ni];
        }
    }
    __syncthreads();
    if (tid < 128) {
        const float t = redbuf[tid * 4 + 0] + redbuf[tid * 4 + 1] +
                        redbuf[tid * 4 + 2] + redbuf[tid * 4 + 3];
        g_Epart[(size_t)tn * KROWS + mbase + tid] = t;
        if (tm != tn) {
            const float cst = colbuf[tid * 2 + 0] + colbuf[tid * 2 + 1];
            g_Epart[(size_t)tm * KROWS + nbase + tid] = cst;
        }
    }
}

// ---------------------------------------------------------------------------
// Kernel 4: per-row NT-Xent loss. One thread per row; 64 blocks x 32 threads.
// ---------------------------------------------------------------------------
__global__ void k_loss() {
    const int tid = threadIdx.x;
    const int i = blockIdx.x * 32 + tid;  // 64*32 = 2048
    float contrib = 0.f;
    {
        const int nrow = i >> 7;  // i / 128
        float esum = 0.f;
#pragma unroll
        for (int t2 = 0; t2 < 16; t2++) esum += g_Epart[t2 * KROWS + i];
        float pv[16], ev[16];
        float esub = 0.f;
#pragma unroll
        for (int m = 0; m < 16; m++) {
            pv[m] = 2.f * g_P[i * 16 + m];
            ev[m] = __expf(pv[m]);
            esub += ev[m];
        }
        const float eneg = esum - esub;  // exp-sum over negatives only
#pragma unroll
        for (int m = 0; m < 16; m++)
            if (m != nrow) contrib += __logf(eneg + ev[m]) - pv[m];
    }
#pragma unroll
    for (int o = 16; o > 0; o >>= 1)
        contrib += __shfl_xor_sync(0xffffffffu, contrib, o);
    if (tid == 0) g_losspart[blockIdx.x] = contrib;
}

// ---------------------------------------------------------------------------
// Kernel 5: final combine (deterministic fixed-order reductions)
// ---------------------------------------------------------------------------
__global__ void k_final(float* __restrict__ out) {
    const int tid = threadIdx.x;
    float s = 0.f;
    for (int j = tid; j < 2048; j += 256) s += g_msepart[j];
    __shared__ float wred[8];
    const int lane = tid & 31, warp = tid >> 5;
#pragma unroll
    for (int o = 16; o > 0; o >>= 1) s += __shfl_xor_sync(0xffffffffu, s, o);
    if (lane == 0) wred[warp] = s;
    __syncthreads();
    if (tid == 0) {
        float mse = 0.f;
#pragma unroll
        for (int j = 0; j < 8; j++) mse += wred[j];
        float l = 0.f;
#pragma unroll
        for (int b = 0; b < 64; b++) l += g_losspart[b];
        out[0] = mse * (1.f / (float)PIC_ELEMS) + l * (1.f / (float)(KROWS * 15));
    }
}

// ---------------------------------------------------------------------------
extern "C" void kernel_launch(void* const* d_in, const int* in_sizes, int n_in,
                              void* d_out, int out_size) {
    (void)in_sizes; (void)n_in; (void)out_size;
    const float* pic = (const float*)d_in[0];
    const float* dec = (const float*)d_in[1];
    const float* h   = (const float*)d_in[2];

    // One-time resource init (host objects only — no device memory).
    // The launched work is identical on every call.
    static cudaStream_t s2 = nullptr;
    static cudaEvent_t ev_fork = nullptr, ev_join = nullptr;
    if (s2 == nullptr) {
        cudaStreamCreateWithFlags(&s2, cudaStreamNonBlocking);
        cudaEventCreateWithFlags(&ev_fork, cudaEventDisableTiming);
        cudaEventCreateWithFlags(&ev_join, cudaEventDisableTiming);
        cudaFuncSetAttribute(k_gemm, cudaFuncAttributeMaxDynamicSharedMemorySize,
                             SMEM_TC);
    }

    // Fork: k_mse (HBM-bound, independent) runs concurrently with the
    // norm -> gemm -> loss chain (compute-bound); join before k_final.
    cudaEventRecord(ev_fork, 0);
    cudaStreamWaitEvent(s2, ev_fork, 0);
    k_mse<<<2048, 256, 0, s2>>>(pic, dec);
    cudaEventRecord(ev_join, s2);

    k_norm<<<KROWS, 256>>>(h);
    k_gemm<<<136, 256, SMEM_TC>>>();
    k_loss<<<64, 32>>>();

    cudaStreamWaitEvent(0, ev_join, 0);
    k_final<<<1, 256>>>((float*)d_out);
}

// round 8
// speedup vs baseline: 1.8015x; 1.0398x over previous
#include <cuda_runtime.h>
#include <cuda_bf16.h>
#include <cuda_fp8.h>
#include <cstdint>

// Problem constants
#define KROWS 2048          // N*BS = 16*128
#define DDIM 4096
#define NTILE 16            // num_transforms, also number of 128-col tiles
#define SLAB 1572864        // BS*C*H*W floats per transform slab
#define PIC_ELEMS 25165824  // N*BS*C*H*W

// Scratch (static device globals; no runtime allocation)
__device__ uint8_t g_sn8[(size_t)KROWS * DDIM];        // normalized h * 64, e4m3 (8 MB)
__device__ float g_Epart[NTILE * KROWS];               // per-column-tile exp row sums
__device__ float g_P[KROWS * 16];                      // same-mod sims (incl diag)
__device__ float g_msepart[256];
__device__ float g_losspart[64];

// ---------------------------------------------------------------------------
// Kernel 1: row L2 norms of h, write (sn * 64) as e4m3
// ---------------------------------------------------------------------------
__global__ void k_norm(const float* __restrict__ h) {
    const int row = blockIdx.x;
    const int tid = threadIdx.x;
    const float4* src = (const float4*)(h + (size_t)row * DDIM);

    // Thread reads 4 consecutive float4 (16 floats, 64 bytes)
    float4 v[4];
    float s = 0.f;
#pragma unroll
    for (int i = 0; i < 4; i++) {
        v[i] = src[tid * 4 + i];
        s += v[i].x * v[i].x + v[i].y * v[i].y + v[i].z * v[i].z + v[i].w * v[i].w;
    }

    __shared__ float wred[8];
    __shared__ float s_inv;
    const int lane = tid & 31, warp = tid >> 5;
#pragma unroll
    for (int o = 16; o > 0; o >>= 1) s += __shfl_xor_sync(0xffffffffu, s, o);
    if (lane == 0) wred[warp] = s;
    __syncthreads();
    if (tid == 0) {
        float t = 0.f;
#pragma unroll
        for (int i = 0; i < 8; i++) t += wred[i];
        s_inv = 64.f / fmaxf(sqrtf(t), 1e-8f);  // fp8 pre-scale folded in
    }
    __syncthreads();
    const float inv = s_inv;

    // 16 floats -> 16 e4m3 bytes -> one uint4 store
    uint32_t packed[4];
#pragma unroll
    for (int i = 0; i < 4; i++) {
        float2 lo = make_float2(v[i].x * inv, v[i].y * inv);
        float2 hi = make_float2(v[i].z * inv, v[i].w * inv);
        const uint32_t plo = __nv_cvt_float2_to_fp8x2(lo, __NV_SATFINITE, __NV_E4M3);
        const uint32_t phi = __nv_cvt_float2_to_fp8x2(hi, __NV_SATFINITE, __NV_E4M3);
        packed[i] = (plo & 0xFFFFu) | (phi << 16);
    }
    uint4 u;
    u.x = packed[0]; u.y = packed[1]; u.z = packed[2]; u.w = packed[3];
    *(uint4*)(g_sn8 + (size_t)row * DDIM + tid * 16) = u;
}

// ---------------------------------------------------------------------------
// Kernel 2: MSE between pic_set[n] and dec_pics[(n+1)%16].
// 256 CTAs only (leaves SM thread slots free so k_gemm co-resides);
// 4x unrolled grid-stride for MLP. 256*256*96 == total4 exactly.
// ---------------------------------------------------------------------------
__global__ void k_mse(const float* __restrict__ pic, const float* __restrict__ dec) {
    const int tid = threadIdx.x;
    const int slab4 = SLAB / 4;
    const int stride = 256 * 256;
    float s = 0.f;
    int i4 = blockIdx.x * 256 + tid;
#pragma unroll 1
    for (int it = 0; it < 24; it++) {
#pragma unroll
        for (int u = 0; u < 4; u++) {
            const int j4 = i4 + u * stride;
            const int n = j4 / slab4;
            const int rem4 = j4 - n * slab4;
            const int di4 = ((n + 1) & 15) * slab4 + rem4;
            const float4 a = *((const float4*)pic + j4);
            const float4 b = *((const float4*)dec + di4);
            const float dx = a.x - b.x, dy = a.y - b.y, dz = a.z - b.z,
                        dw = a.w - b.w;
            s += dx * dx + dy * dy + dz * dz + dw * dw;
        }
        i4 += 4 * stride;
    }
    __shared__ float wred[8];
    const int lane = tid & 31, warp = tid >> 5;
#pragma unroll
    for (int o = 16; o > 0; o >>= 1) s += __shfl_xor_sync(0xffffffffu, s, o);
    if (lane == 0) wred[warp] = s;
    __syncthreads();
    if (tid == 0) {
        float t = 0.f;
#pragma unroll
        for (int i = 0; i < 8; i++) t += wred[i];
        g_msepart[blockIdx.x] = t;
    }
}

// ---------------------------------------------------------------------------
// Kernel 3: FP8 e4m3 mma.sync GEMM  sim_raw = (64 sn)(64 sn)^T, upper-tri
// tiles (136 = 1 wave), cp.async 4-stage BK=128 bytes, fused exp row/col-sum
// epilogue (descale 1/4096) and tile-diagonal capture both ways.
// Block: 128x128 tile, 8 warps (2x4), warp tile 64x32.
// ---------------------------------------------------------------------------
#define LDSS8 144                    // smem row stride bytes (128 + 16 pad)
#define TILE8 (128 * LDSS8)          // 18432 bytes per tile buffer
#define STAGEB (2 * TILE8)           // A+B per stage = 36864
#define STAGES 4
#define SMEM_TC (STAGES * STAGEB)    // 147456 bytes

__device__ __forceinline__ uint32_t smem_u32(const void* p) {
    return (uint32_t)__cvta_generic_to_shared(p);
}

__device__ __forceinline__ void cp_async16(uint32_t s, const void* g) {
    asm volatile("cp.async.cg.shared.global [%0], [%1], 16;\n" :: "r"(s), "l"(g));
}

__device__ __forceinline__ void ldsm4(uint32_t& r0, uint32_t& r1, uint32_t& r2,
                                      uint32_t& r3, uint32_t a) {
    asm volatile("ldmatrix.sync.aligned.m8n8.x4.shared.b16 {%0,%1,%2,%3}, [%4];\n"
                 : "=r"(r0), "=r"(r1), "=r"(r2), "=r"(r3)
                 : "r"(a));
}

__device__ __forceinline__ void mma16832(float c[4], const uint32_t a[4],
                                         const uint32_t b[2]) {
    asm volatile(
        "mma.sync.aligned.m16n8k32.row.col.f32.e4m3.e4m3.f32 "
        "{%0,%1,%2,%3}, {%4,%5,%6,%7}, {%8,%9}, {%0,%1,%2,%3};\n"
        : "+f"(c[0]), "+f"(c[1]), "+f"(c[2]), "+f"(c[3])
        : "r"(a[0]), "r"(a[1]), "r"(a[2]), "r"(a[3]), "r"(b[0]), "r"(b[1]));
}

__global__ void __launch_bounds__(256) k_gemm() {
    extern __shared__ char smem[];
    const int tid = threadIdx.x;
    const int warp = tid >> 5, lane = tid & 31;
    const int wm = warp >> 2, wn = warp & 3;

    // Decode upper-triangular tile index: blockIdx.x in [0,136)
    int bidx = blockIdx.x, tm = 0;
    while (bidx >= 16 - tm) { bidx -= 16 - tm; tm++; }
    const int tn = tm + bidx;
    const int mbase = tm * 128, nbase = tn * 128;

    float acc[4][4][4];
#pragma unroll
    for (int i = 0; i < 4; i++)
#pragma unroll
        for (int j = 0; j < 4; j++)
#pragma unroll
            for (int k = 0; k < 4; k++) acc[i][j][k] = 0.f;

    // Loader: BK=128 bytes chunk (128 rows x 128B) for A and B via cp.async
    auto load_chunk = [&](int c, int stg) {
        const uint32_t sa = smem_u32(smem + stg * STAGEB);
        const uint32_t sbm = sa + TILE8;
#pragma unroll
        for (int i = 0; i < 4; i++) {
            const int idx = tid + i * 256;  // 0..1023
            const int row = idx >> 3;       // 0..127
            const int c16 = idx & 7;        // 16B chunk within 128B row
            const uint32_t so = (uint32_t)(row * LDSS8 + c16 * 16);
            cp_async16(sa + so,
                       g_sn8 + (size_t)(mbase + row) * DDIM + (c << 7) + c16 * 16);
            cp_async16(sbm + so,
                       g_sn8 + (size_t)(nbase + row) * DDIM + (c << 7) + c16 * 16);
        }
        asm volatile("cp.async.commit_group;\n" ::: "memory");
    };

    // ldmatrix byte-granule addressing (identical fragment map to bf16, in
    // 16B units): A x4 -> a0..a3 of m16n8k32; B x4 -> two n-blocks' {b0,b1}.
    const int a_row_off = ((lane >> 3) & 1) * 8 + (lane & 7);
    const int a_col_off = ((lane >> 4) & 1) * 16;  // bytes
    const int b_grp = lane >> 3;
    const int b_row_off = (b_grp >> 1) * 8 + (lane & 7);
    const int b_col_off = (b_grp & 1) * 16;        // bytes

#pragma unroll
    for (int s = 0; s < STAGES - 1; s++) load_chunk(s, s);

    for (int c = 0; c < 32; c++) {
        const int stg = c & (STAGES - 1);
        if (c + STAGES - 1 < 32) load_chunk(c + STAGES - 1, (c + STAGES - 1) & (STAGES - 1));
        if (c <= 28) {
            asm volatile("cp.async.wait_group 3;\n" ::: "memory");
        } else if (c == 29) {
            asm volatile("cp.async.wait_group 2;\n" ::: "memory");
        } else if (c == 30) {
            asm volatile("cp.async.wait_group 1;\n" ::: "memory");
        } else {
            asm volatile("cp.async.wait_group 0;\n" ::: "memory");
        }
        __syncthreads();

        const char* As = smem + stg * STAGEB;
        const char* Bs = smem + stg * STAGEB + TILE8;
#pragma unroll
        for (int ksb = 0; ksb < 128; ksb += 32) {  // 32 e4m3 per mma k-step
            uint32_t a[4][4], b[4][2];
#pragma unroll
            for (int mi = 0; mi < 4; mi++) {
                const uint32_t ad = smem_u32(
                    As + (wm * 64 + mi * 16 + a_row_off) * LDSS8 + ksb + a_col_off);
                ldsm4(a[mi][0], a[mi][1], a[mi][2], a[mi][3], ad);
            }
#pragma unroll
            for (int nb = 0; nb < 2; nb++) {
                const uint32_t ad = smem_u32(
                    Bs + (wn * 32 + nb * 16 + b_row_off) * LDSS8 + ksb + b_col_off);
                uint32_t r0, r1, r2, r3;
                ldsm4(r0, r1, r2, r3, ad);
                b[nb * 2][0] = r0;
                b[nb * 2][1] = r1;
                b[nb * 2 + 1][0] = r2;
                b[nb * 2 + 1][1] = r3;
            }
#pragma unroll
            for (int mi = 0; mi < 4; mi++)
#pragma unroll
                for (int ni = 0; ni < 4; ni++) mma16832(acc[mi][ni], a[mi], b[ni]);
        }
        __syncthreads();  // all warps done with stage stg before reload
    }

    // Epilogue. acc holds 4096*sim. logit = 2*sim = acc/2048; g_P stores sim.
    const float LGSCALE = 1.f / 2048.f;
    const float SIMSCALE = 1.f / 4096.f;
    float* redbuf = (float*)smem;            // 128 rows x 4 wn-warps
    float* colbuf = (float*)smem + 512;      // 128 cols x 2 wm-warps
    const int quad = lane >> 2, tid4 = lane & 3;

    float cs0[4], cs1[4];
#pragma unroll
    for (int ni = 0; ni < 4; ni++) { cs0[ni] = 0.f; cs1[ni] = 0.f; }

#pragma unroll
    for (int mi = 0; mi < 4; mi++) {
        float s0 = 0.f, s1 = 0.f;
        const int r0l = wm * 64 + mi * 16 + quad;
#pragma unroll
        for (int ni = 0; ni < 4; ni++) {
            const int c0l = wn * 32 + ni * 8 + tid4 * 2;
            const float v0 = acc[mi][ni][0], v1 = acc[mi][ni][1];
            const float v2 = acc[mi][ni][2], v3 = acc[mi][ni][3];
            const float e0 = __expf(LGSCALE * v0), e1 = __expf(LGSCALE * v1);
            const float e2 = __expf(LGSCALE * v2), e3 = __expf(LGSCALE * v3);
            s0 += e0 + e1;
            s1 += e2 + e3;
            cs0[ni] += e0 + e2;
            cs1[ni] += e1 + e3;
            if (r0l == c0l) {
                g_P[(size_t)(mbase + r0l) * 16 + tn] = v0 * SIMSCALE;
                if (tm != tn) g_P[(size_t)(nbase + c0l) * 16 + tm] = v0 * SIMSCALE;
            }
            if (r0l == c0l + 1) {
                g_P[(size_t)(mbase + r0l) * 16 + tn] = v1 * SIMSCALE;
                if (tm != tn) g_P[(size_t)(nbase + c0l + 1) * 16 + tm] = v1 * SIMSCALE;
            }
            if (r0l + 8 == c0l) {
                g_P[(size_t)(mbase + r0l + 8) * 16 + tn] = v2 * SIMSCALE;
                if (tm != tn) g_P[(size_t)(nbase + c0l) * 16 + tm] = v2 * SIMSCALE;
            }
            if (r0l + 8 == c0l + 1) {
                g_P[(size_t)(mbase + r0l + 8) * 16 + tn] = v3 * SIMSCALE;
                if (tm != tn) g_P[(size_t)(nbase + c0l + 1) * 16 + tm] = v3 * SIMSCALE;
            }
        }
        s0 += __shfl_xor_sync(0xffffffffu, s0, 1);
        s0 += __shfl_xor_sync(0xffffffffu, s0, 2);
        s1 += __shfl_xor_sync(0xffffffffu, s1, 1);
        s1 += __shfl_xor_sync(0xffffffffu, s1, 2);
        if (tid4 == 0) {
            redbuf[r0l * 4 + wn] = s0;
            redbuf[(r0l + 8) * 4 + wn] = s1;
        }
    }
    // Column reduce across the 8 quads (lanes differing in bits 2..4)
#pragma unroll
    for (int ni = 0; ni < 4; ni++) {
#pragma unroll
        for (int o = 4; o < 32; o <<= 1) {
            cs0[ni] += __shfl_xor_sync(0xffffffffu, cs0[ni], o);
            cs1[ni] += __shfl_xor_sync(0xffffffffu, cs1[ni], o);
        }
        if (lane < 4) {  // quad==0, tid4==lane
            const int col = wn * 32 + ni * 8 + lane * 2;
            colbuf[col * 2 + wm] = cs0[ni];
            colbuf[(col + 1) * 2 + wm] = cs1[ni];
        }
    }
    __syncthreads();
    if (tid < 128) {
        const float t = redbuf[tid * 4 + 0] + redbuf[tid * 4 + 1] +
                        redbuf[tid * 4 + 2] + redbuf[tid * 4 + 3];
        g_Epart[(size_t)tn * KROWS + mbase + tid] = t;
        if (tm != tn) {
            const float cst = colbuf[tid * 2 + 0] + colbuf[tid * 2 + 1];
            g_Epart[(size_t)tm * KROWS + nbase + tid] = cst;
        }
    }
}

// ---------------------------------------------------------------------------
// Kernel 4: per-row NT-Xent loss. One thread per row; 64 blocks x 32 threads.
// ---------------------------------------------------------------------------
__global__ void k_loss() {
    const int tid = threadIdx.x;
    const int i = blockIdx.x * 32 + tid;  // 64*32 = 2048
    float contrib = 0.f;
    {
        const int nrow = i >> 7;  // i / 128
        float esum = 0.f;
#pragma unroll
        for (int t2 = 0; t2 < 16; t2++) esum += g_Epart[t2 * KROWS + i];
        float pv[16], ev[16];
        float esub = 0.f;
#pragma unroll
        for (int m = 0; m < 16; m++) {
            pv[m] = 2.f * g_P[i * 16 + m];
            ev[m] = __expf(pv[m]);
            esub += ev[m];
        }
        const float eneg = esum - esub;  // exp-sum over negatives only
#pragma unroll
        for (int m = 0; m < 16; m++)
            if (m != nrow) contrib += __logf(eneg + ev[m]) - pv[m];
    }
#pragma unroll
    for (int o = 16; o > 0; o >>= 1)
        contrib += __shfl_xor_sync(0xffffffffu, contrib, o);
    if (tid == 0) g_losspart[blockIdx.x] = contrib;
}

// ---------------------------------------------------------------------------
// Kernel 5: final combine (deterministic fixed-order reductions)
// ---------------------------------------------------------------------------
__global__ void k_final(float* __restrict__ out) {
    const int tid = threadIdx.x;
    float s = (tid < 256) ? g_msepart[tid] : 0.f;
    __shared__ float wred[8];
    const int lane = tid & 31, warp = tid >> 5;
#pragma unroll
    for (int o = 16; o > 0; o >>= 1) s += __shfl_xor_sync(0xffffffffu, s, o);
    if (lane == 0) wred[warp] = s;
    __syncthreads();
    if (tid == 0) {
        float mse = 0.f;
#pragma unroll
        for (int j = 0; j < 8; j++) mse += wred[j];
        float l = 0.f;
#pragma unroll
        for (int b = 0; b < 64; b++) l += g_losspart[b];
        out[0] = mse * (1.f / (float)PIC_ELEMS) + l * (1.f / (float)(KROWS * 15));
    }
}

// ---------------------------------------------------------------------------
extern "C" void kernel_launch(void* const* d_in, const int* in_sizes, int n_in,
                              void* d_out, int out_size) {
    (void)in_sizes; (void)n_in; (void)out_size;
    const float* pic = (const float*)d_in[0];
    const float* dec = (const float*)d_in[1];
    const float* h   = (const float*)d_in[2];

    // One-time host-object init (no device memory). Launched work is
    // identical on every call.
    static cudaStream_t s2 = nullptr;
    static cudaEvent_t ev_fork = nullptr, ev_join = nullptr;
    if (s2 == nullptr) {
        cudaStreamCreateWithFlags(&s2, cudaStreamNonBlocking);
        cudaEventCreateWithFlags(&ev_fork, cudaEventDisableTiming);
        cudaEventCreateWithFlags(&ev_join, cudaEventDisableTiming);
        cudaFuncSetAttribute(k_gemm, cudaFuncAttributeMaxDynamicSharedMemorySize,
                             SMEM_TC);
    }

    // Fork: k_mse (DRAM-bound, 256 CTAs so it co-resides with the GEMM)
    // overlaps the norm -> gemm -> loss chain; join before k_final.
    cudaEventRecord(ev_fork, 0);
    cudaStreamWaitEvent(s2, ev_fork, 0);
    k_mse<<<256, 256, 0, s2>>>(pic, dec);
    cudaEventRecord(ev_join, s2);

    k_norm<<<KROWS, 256>>>(h);
    k_gemm<<<136, 256, SMEM_TC>>>();
    k_loss<<<64, 32>>>();

    cudaStreamWaitEvent(0, ev_join, 0);
    k_final<<<1, 256>>>((float*)d_out);
}

// round 9
// speedup vs baseline: 2.0565x; 1.1415x over previous
#include <cuda_runtime.h>
#include <cuda_bf16.h>
#include <cuda_fp8.h>
#include <cstdint>

// Problem constants
#define KROWS 2048          // N*BS = 16*128
#define DDIM 4096
#define NTILE 16            // num_transforms, also number of 128-col tiles
#define SLAB 1572864        // BS*C*H*W floats per transform slab
#define PIC_ELEMS 25165824  // N*BS*C*H*W

#define NB_GEMM 136
#define NB_MSE 160
#define NB_TOTAL (NB_GEMM + NB_MSE)  // 296 = 2 blocks x 148 SMs

// Scratch (static device globals; no runtime allocation)
__device__ uint8_t g_sn8[(size_t)KROWS * DDIM];  // normalized h * 64, e4m3 (8 MB)
__device__ float g_Epart[KROWS * 16];            // [row][tile] exp row sums
__device__ float g_P[KROWS * 16];                // same-mod sims (incl diag)
__device__ float g_msepart[NB_MSE];
__device__ float g_losspart[64];

// ---------------------------------------------------------------------------
// Kernel 1: row L2 norms of h, write (sn * 64) as e4m3
// ---------------------------------------------------------------------------
__global__ void k_norm(const float* __restrict__ h) {
    const int row = blockIdx.x;
    const int tid = threadIdx.x;
    const float4* src = (const float4*)(h + (size_t)row * DDIM);

    float4 v[4];
    float s = 0.f;
#pragma unroll
    for (int i = 0; i < 4; i++) {
        v[i] = src[tid * 4 + i];
        s += v[i].x * v[i].x + v[i].y * v[i].y + v[i].z * v[i].z + v[i].w * v[i].w;
    }

    __shared__ float wred[8];
    __shared__ float s_inv;
    const int lane = tid & 31, warp = tid >> 5;
#pragma unroll
    for (int o = 16; o > 0; o >>= 1) s += __shfl_xor_sync(0xffffffffu, s, o);
    if (lane == 0) wred[warp] = s;
    __syncthreads();
    if (tid == 0) {
        float t = 0.f;
#pragma unroll
        for (int i = 0; i < 8; i++) t += wred[i];
        s_inv = 64.f / fmaxf(sqrtf(t), 1e-8f);  // fp8 pre-scale folded in
    }
    __syncthreads();
    const float inv = s_inv;

    uint32_t packed[4];
#pragma unroll
    for (int i = 0; i < 4; i++) {
        float2 lo = make_float2(v[i].x * inv, v[i].y * inv);
        float2 hi = make_float2(v[i].z * inv, v[i].w * inv);
        const uint32_t plo = __nv_cvt_float2_to_fp8x2(lo, __NV_SATFINITE, __NV_E4M3);
        const uint32_t phi = __nv_cvt_float2_to_fp8x2(hi, __NV_SATFINITE, __NV_E4M3);
        packed[i] = (plo & 0xFFFFu) | (phi << 16);
    }
    uint4 u;
    u.x = packed[0]; u.y = packed[1]; u.z = packed[2]; u.w = packed[3];
    *(uint4*)(g_sn8 + (size_t)row * DDIM + tid * 16) = u;
}

// ---------------------------------------------------------------------------
// Fused kernel: blocks [0,136) run the FP8 GEMM tile; blocks [136,296) run
// the MSE stream. 2 blocks/SM (110.6 KB smem each) => gemm gets one SM's
// tensor pipe to itself while an mse block streams DRAM on the same SM.
// ---------------------------------------------------------------------------
#define LDSS8 144                    // smem row stride bytes (128 + 16 pad)
#define TILE8 (128 * LDSS8)          // 18432 bytes per tile buffer
#define STAGEB (2 * TILE8)           // A+B per stage = 36864
#define STAGES 3
#define SMEM_TC (STAGES * STAGEB)    // 110592 bytes

__device__ __forceinline__ uint32_t smem_u32(const void* p) {
    return (uint32_t)__cvta_generic_to_shared(p);
}

__device__ __forceinline__ void cp_async16(uint32_t s, const void* g) {
    asm volatile("cp.async.cg.shared.global [%0], [%1], 16;\n" :: "r"(s), "l"(g));
}

__device__ __forceinline__ void ldsm4(uint32_t& r0, uint32_t& r1, uint32_t& r2,
                                      uint32_t& r3, uint32_t a) {
    asm volatile("ldmatrix.sync.aligned.m8n8.x4.shared.b16 {%0,%1,%2,%3}, [%4];\n"
                 : "=r"(r0), "=r"(r1), "=r"(r2), "=r"(r3)
                 : "r"(a));
}

__device__ __forceinline__ void mma16832(float c[4], const uint32_t a[4],
                                         const uint32_t b[2]) {
    asm volatile(
        "mma.sync.aligned.m16n8k32.row.col.f32.e4m3.e4m3.f32 "
        "{%0,%1,%2,%3}, {%4,%5,%6,%7}, {%8,%9}, {%0,%1,%2,%3};\n"
        : "+f"(c[0]), "+f"(c[1]), "+f"(c[2]), "+f"(c[3])
        : "r"(a[0]), "r"(a[1]), "r"(a[2]), "r"(a[3]), "r"(b[0]), "r"(b[1]));
}

__global__ void __launch_bounds__(256, 2) k_gm(const float* __restrict__ pic,
                                               const float* __restrict__ dec) {
    extern __shared__ char smem[];
    const int tid = threadIdx.x;

    if (blockIdx.x >= NB_GEMM) {
        // ---------------- MSE branch ----------------
        const int mb = blockIdx.x - NB_GEMM;
        const int total4 = PIC_ELEMS / 4;
        const int slab4 = SLAB / 4;
        float s = 0.f;
        for (int i4 = mb * 256 + tid; i4 < total4; i4 += NB_MSE * 256) {
            const int n = i4 / slab4;
            const int rem4 = i4 - n * slab4;
            const int di4 = ((n + 1) & 15) * slab4 + rem4;
            const float4 a = *((const float4*)pic + i4);
            const float4 b = *((const float4*)dec + di4);
            const float dx = a.x - b.x, dy = a.y - b.y, dz = a.z - b.z,
                        dw = a.w - b.w;
            s += dx * dx + dy * dy + dz * dz + dw * dw;
        }
        __shared__ float wredm[8];
        const int lane = tid & 31, warp = tid >> 5;
#pragma unroll
        for (int o = 16; o > 0; o >>= 1) s += __shfl_xor_sync(0xffffffffu, s, o);
        if (lane == 0) wredm[warp] = s;
        __syncthreads();
        if (tid == 0) {
            float t = 0.f;
#pragma unroll
            for (int i = 0; i < 8; i++) t += wredm[i];
            g_msepart[mb] = t;
        }
        return;
    }

    // ---------------- GEMM branch ----------------
    const int warp = tid >> 5, lane = tid & 31;
    const int wm = warp >> 2, wn = warp & 3;

    // Decode upper-triangular tile index: blockIdx.x in [0,136)
    int bidx = blockIdx.x, tm = 0;
    while (bidx >= 16 - tm) { bidx -= 16 - tm; tm++; }
    const int tn = tm + bidx;
    const int mbase = tm * 128, nbase = tn * 128;

    float acc[4][4][4];
#pragma unroll
    for (int i = 0; i < 4; i++)
#pragma unroll
        for (int j = 0; j < 4; j++)
#pragma unroll
            for (int k = 0; k < 4; k++) acc[i][j][k] = 0.f;

    // Loader: 128-byte K chunk (128 rows x 128B) for A and B via cp.async
    auto load_chunk = [&](int c, int stg) {
        const uint32_t sa = smem_u32(smem + stg * STAGEB);
        const uint32_t sbm = sa + TILE8;
#pragma unroll
        for (int i = 0; i < 4; i++) {
            const int idx = tid + i * 256;  // 0..1023
            const int row = idx >> 3;       // 0..127
            const int c16 = idx & 7;        // 16B chunk within 128B row
            const uint32_t so = (uint32_t)(row * LDSS8 + c16 * 16);
            cp_async16(sa + so,
                       g_sn8 + (size_t)(mbase + row) * DDIM + (c << 7) + c16 * 16);
            cp_async16(sbm + so,
                       g_sn8 + (size_t)(nbase + row) * DDIM + (c << 7) + c16 * 16);
        }
        asm volatile("cp.async.commit_group;\n" ::: "memory");
    };

    // ldmatrix byte-granule addressing (16B units)
    const int a_row_off = ((lane >> 3) & 1) * 8 + (lane & 7);
    const int a_col_off = ((lane >> 4) & 1) * 16;  // bytes
    const int b_grp = lane >> 3;
    const int b_row_off = (b_grp >> 1) * 8 + (lane & 7);
    const int b_col_off = (b_grp & 1) * 16;        // bytes

    load_chunk(0, 0);
    load_chunk(1, 1);

    for (int c = 0; c < 32; c++) {
        const int stg = c % STAGES;
        // chunk c's group complete (allow 1 newer pending)
        if (c < 31) {
            asm volatile("cp.async.wait_group 1;\n" ::: "memory");
        } else {
            asm volatile("cp.async.wait_group 0;\n" ::: "memory");
        }
        __syncthreads();  // also guards stage (c+2)%3 from lagging readers
        if (c + 2 < 32) load_chunk(c + 2, (c + 2) % STAGES);

        const char* As = smem + stg * STAGEB;
        const char* Bs = smem + stg * STAGEB + TILE8;
#pragma unroll
        for (int ksb = 0; ksb < 128; ksb += 32) {  // 32 e4m3 per mma k-step
            uint32_t a[4][4], b[4][2];
#pragma unroll
            for (int mi = 0; mi < 4; mi++) {
                const uint32_t ad = smem_u32(
                    As + (wm * 64 + mi * 16 + a_row_off) * LDSS8 + ksb + a_col_off);
                ldsm4(a[mi][0], a[mi][1], a[mi][2], a[mi][3], ad);
            }
#pragma unroll
            for (int nb = 0; nb < 2; nb++) {
                const uint32_t ad = smem_u32(
                    Bs + (wn * 32 + nb * 16 + b_row_off) * LDSS8 + ksb + b_col_off);
                uint32_t r0, r1, r2, r3;
                ldsm4(r0, r1, r2, r3, ad);
                b[nb * 2][0] = r0;
                b[nb * 2][1] = r1;
                b[nb * 2 + 1][0] = r2;
                b[nb * 2 + 1][1] = r3;
            }
#pragma unroll
            for (int mi = 0; mi < 4; mi++)
#pragma unroll
                for (int ni = 0; ni < 4; ni++) mma16832(acc[mi][ni], a[mi], b[ni]);
        }
    }
    __syncthreads();  // all warps done with mainloop before smem reuse below

    // Epilogue. acc holds 4096*sim. logit = 2*sim = acc/2048; g_P stores sim.
    const float LGSCALE = 1.f / 2048.f;
    const float SIMSCALE = 1.f / 4096.f;
    float* redbuf = (float*)smem;            // 128 rows x 4 wn-warps
    float* colbuf = (float*)smem + 512;      // 128 cols x 2 wm-warps
    const int quad = lane >> 2, tid4 = lane & 3;

    float cs0[4], cs1[4];
#pragma unroll
    for (int ni = 0; ni < 4; ni++) { cs0[ni] = 0.f; cs1[ni] = 0.f; }

#pragma unroll
    for (int mi = 0; mi < 4; mi++) {
        float s0 = 0.f, s1 = 0.f;
        const int r0l = wm * 64 + mi * 16 + quad;
#pragma unroll
        for (int ni = 0; ni < 4; ni++) {
            const int c0l = wn * 32 + ni * 8 + tid4 * 2;
            const float v0 = acc[mi][ni][0], v1 = acc[mi][ni][1];
            const float v2 = acc[mi][ni][2], v3 = acc[mi][ni][3];
            const float e0 = __expf(LGSCALE * v0), e1 = __expf(LGSCALE * v1);
            const float e2 = __expf(LGSCALE * v2), e3 = __expf(LGSCALE * v3);
            s0 += e0 + e1;
            s1 += e2 + e3;
            cs0[ni] += e0 + e2;
            cs1[ni] += e1 + e3;
            if (r0l == c0l) {
                g_P[(size_t)(mbase + r0l) * 16 + tn] = v0 * SIMSCALE;
                if (tm != tn) g_P[(size_t)(nbase + c0l) * 16 + tm] = v0 * SIMSCALE;
            }
            if (r0l == c0l + 1) {
                g_P[(size_t)(mbase + r0l) * 16 + tn] = v1 * SIMSCALE;
                if (tm != tn) g_P[(size_t)(nbase + c0l + 1) * 16 + tm] = v1 * SIMSCALE;
            }
            if (r0l + 8 == c0l) {
                g_P[(size_t)(mbase + r0l + 8) * 16 + tn] = v2 * SIMSCALE;
                if (tm != tn) g_P[(size_t)(nbase + c0l) * 16 + tm] = v2 * SIMSCALE;
            }
            if (r0l + 8 == c0l + 1) {
                g_P[(size_t)(mbase + r0l + 8) * 16 + tn] = v3 * SIMSCALE;
                if (tm != tn) g_P[(size_t)(nbase + c0l + 1) * 16 + tm] = v3 * SIMSCALE;
            }
        }
        s0 += __shfl_xor_sync(0xffffffffu, s0, 1);
        s0 += __shfl_xor_sync(0xffffffffu, s0, 2);
        s1 += __shfl_xor_sync(0xffffffffu, s1, 1);
        s1 += __shfl_xor_sync(0xffffffffu, s1, 2);
        if (tid4 == 0) {
            redbuf[r0l * 4 + wn] = s0;
            redbuf[(r0l + 8) * 4 + wn] = s1;
        }
    }
    // Column reduce across the 8 quads (lanes differing in bits 2..4)
#pragma unroll
    for (int ni = 0; ni < 4; ni++) {
#pragma unroll
        for (int o = 4; o < 32; o <<= 1) {
            cs0[ni] += __shfl_xor_sync(0xffffffffu, cs0[ni], o);
            cs1[ni] += __shfl_xor_sync(0xffffffffu, cs1[ni], o);
        }
        if (lane < 4) {  // quad==0, tid4==lane
            const int col = wn * 32 + ni * 8 + lane * 2;
            colbuf[col * 2 + wm] = cs0[ni];
            colbuf[(col + 1) * 2 + wm] = cs1[ni];
        }
    }
    __syncthreads();
    if (tid < 128) {
        // Epart is [row][tile] so k_loss reads 16 contiguous floats per row.
        const float t = redbuf[tid * 4 + 0] + redbuf[tid * 4 + 1] +
                        redbuf[tid * 4 + 2] + redbuf[tid * 4 + 3];
        g_Epart[(size_t)(mbase + tid) * 16 + tn] = t;
        if (tm != tn) {
            const float cst = colbuf[tid * 2 + 0] + colbuf[tid * 2 + 1];
            g_Epart[(size_t)(nbase + tid) * 16 + tm] = cst;
        }
    }
}

// ---------------------------------------------------------------------------
// Kernel 3: per-row NT-Xent loss. One thread per row; 64 blocks x 32 threads.
// Epart/P are [row][16] contiguous -> coalesced 64B reads per thread.
// ---------------------------------------------------------------------------
__global__ void k_loss() {
    const int tid = threadIdx.x;
    const int i = blockIdx.x * 32 + tid;  // 64*32 = 2048
    float contrib = 0.f;
    {
        const int nrow = i >> 7;  // i / 128
        float4 ep[4], pp[4];
#pragma unroll
        for (int q = 0; q < 4; q++) {
            ep[q] = *((const float4*)(g_Epart + i * 16) + q);
            pp[q] = *((const float4*)(g_P + i * 16) + q);
        }
        const float* epf = (const float*)ep;
        const float* ppf = (const float*)pp;
        float esum = 0.f;
        float pv[16], ev[16];
        float esub = 0.f;
#pragma unroll
        for (int m = 0; m < 16; m++) {
            esum += epf[m];
            pv[m] = 2.f * ppf[m];
            ev[m] = __expf(pv[m]);
            esub += ev[m];
        }
        const float eneg = esum - esub;  // exp-sum over negatives only
#pragma unroll
        for (int m = 0; m < 16; m++)
            if (m != nrow) contrib += __logf(eneg + ev[m]) - pv[m];
    }
#pragma unroll
    for (int o = 16; o > 0; o >>= 1)
        contrib += __shfl_xor_sync(0xffffffffu, contrib, o);
    if (tid == 0) g_losspart[blockIdx.x] = contrib;
}

// ---------------------------------------------------------------------------
// Kernel 4: final combine (deterministic fixed-order reductions)
// ---------------------------------------------------------------------------
__global__ void k_final(float* __restrict__ out) {
    const int tid = threadIdx.x;
    float s = (tid < NB_MSE) ? g_msepart[tid] : 0.f;
    __shared__ float wred[8];
    const int lane = tid & 31, warp = tid >> 5;
#pragma unroll
    for (int o = 16; o > 0; o >>= 1) s += __shfl_xor_sync(0xffffffffu, s, o);
    if (lane == 0) wred[warp] = s;
    __syncthreads();
    if (tid == 0) {
        float mse = 0.f;
#pragma unroll
        for (int j = 0; j < 8; j++) mse += wred[j];
        float l = 0.f;
#pragma unroll
        for (int b = 0; b < 64; b++) l += g_losspart[b];
        out[0] = mse * (1.f / (float)PIC_ELEMS) + l * (1.f / (float)(KROWS * 15));
    }
}

// ---------------------------------------------------------------------------
extern "C" void kernel_launch(void* const* d_in, const int* in_sizes, int n_in,
                              void* d_out, int out_size) {
    (void)in_sizes; (void)n_in; (void)out_size;
    const float* pic = (const float*)d_in[0];
    const float* dec = (const float*)d_in[1];
    const float* h   = (const float*)d_in[2];

    // Idempotent host-side attribute set (no device memory, no stream work).
    cudaFuncSetAttribute(k_gm, cudaFuncAttributeMaxDynamicSharedMemorySize,
                         SMEM_TC);

    k_norm<<<KROWS, 256>>>(h);
    k_gm<<<NB_TOTAL, 256, SMEM_TC>>>(pic, dec);
    k_loss<<<64, 32>>>();
    k_final<<<1, 256>>>((float*)d_out);
}